// round 8
// baseline (speedup 1.0000x reference)
#include <cuda_runtime.h>

#define ULL unsigned long long

__device__ float g_Qp[256 * 9216];
__device__ float g_V[9216 * 64];     // V[p][c]
__device__ float g_cA[8 * 256];
__device__ float g_cB[256];
__device__ float g_cC[256];

__device__ __forceinline__ ULL pack2(float lo, float hi) {
    ULL r;
    asm("mov.b64 %0, {%1, %2};" : "=l"(r)
        : "r"(__float_as_uint(lo)), "r"(__float_as_uint(hi)));
    return r;
}
__device__ __forceinline__ void unpack2(ULL v, float& lo, float& hi) {
    unsigned a, b;
    asm("mov.b64 {%0, %1}, %2;" : "=r"(a), "=r"(b) : "l"(v));
    lo = __uint_as_float(a);
    hi = __uint_as_float(b);
}
__device__ __forceinline__ void fma2(ULL& d, ULL a, ULL b) {
    asm("fma.rn.f32x2 %0, %1, %2, %0;" : "+l"(d) : "l"(a), "l"(b));
}
__device__ __forceinline__ void mul2(ULL& d, ULL a) {
    asm("mul.rn.f32x2 %0, %0, %1;" : "+l"(d) : "l"(a));
}

#define HBAR(id) asm volatile("bar.sync %0, 256;" :: "r"(id) : "memory")

// ---------------- kernel 1: per-feature coefficients ----------------
__global__ void coef_kernel(const float* __restrict__ WQ_task,
                            const float* __restrict__ BQ_task,
                            const float* __restrict__ WK_task,
                            const float* __restrict__ WQ_tm1,
                            const float* __restrict__ WQ_x,
                            const float* __restrict__ BQ,
                            const float* __restrict__ WK_x) {
    int f = threadIdx.x;
    float kA = WK_task[f] * WK_x[f];
    float sW = 0.f, sB = 0.f;
#pragma unroll
    for (int h = 0; h < 8; h++) {
        float wq = WQ_task[h * 256 + f];
        sW += wq;
        sB += wq * BQ[h * 256 + f] + BQ_task[h * 256 + f];
        g_cA[h * 256 + f] = kA * wq * WQ_tm1[h * 256 + f];
    }
    g_cB[f] = kA * WQ_x[f] * sW;
    g_cC[f] = kA * sB;
}

// ---------------- kernel 2: build Q' ----------------
__global__ void qprep_kernel(const float* __restrict__ X,
                             const float* __restrict__ prevQ) {
    int f = blockIdx.y;
    int p = blockIdx.x * 256 + threadIdx.x;
    float q = fmaf(g_cB[f], X[f * 9216 + p], g_cC[f]);
#pragma unroll
    for (int h = 0; h < 8; h++)
        q = fmaf(g_cA[h * 256 + f], prevQ[(h * 256 + f) * 9216 + p], q);
    g_Qp[f * 9216 + p] = q;
}

// ---------------- kernel 3: 3x3 conv (F=256->C=64) + affine, writes V[p][c] ----------------
__global__ void __launch_bounds__(256) conv_kernel(const float* __restrict__ X,
                                                   const float* __restrict__ Wc,
                                                   const float* __restrict__ Bc,
                                                   const float* __restrict__ WV,
                                                   const float* __restrict__ BV) {
    __shared__ float sx[4 * 294];
    __shared__ float sw[4 * 288];
    const int tid = threadIdx.x;
    const int w = blockIdx.x;
    const int cbase = blockIdx.y * 32;
    const int cl = tid >> 3;
    const int c = cbase + cl;
    const int h0 = (tid & 7) * 12;

    float acc[12];
#pragma unroll
    for (int i = 0; i < 12; i++) acc[i] = 0.f;

    for (int fc = 0; fc < 256; fc += 4) {
        __syncthreads();
        for (int i = tid; i < 4 * 294; i += 256) {
            int ff = i / 294, r = i % 294;
            int dw = r / 98, hh = r % 98;
            int ww = w + dw - 1;
            float v = 0.f;
            if (ww >= 0 && ww < 96 && hh >= 1 && hh <= 96)
                v = X[(fc + ff) * 9216 + ww * 96 + hh - 1];
            sx[i] = v;
        }
        for (int i = tid; i < 4 * 288; i += 256) {
            int ff = i / 288, r = i % 288;
            int ccl = r / 9, s = r % 9;
            sw[i] = Wc[((cbase + ccl) * 256 + fc + ff) * 9 + s];
        }
        __syncthreads();
#pragma unroll
        for (int ff = 0; ff < 4; ff++) {
            float wv[9];
#pragma unroll
            for (int s = 0; s < 9; s++) wv[s] = sw[ff * 288 + cl * 9 + s];
#pragma unroll
            for (int dw = 0; dw < 3; dw++) {
                float xr[14];
#pragma unroll
                for (int j = 0; j < 14; j++) xr[j] = sx[ff * 294 + dw * 98 + h0 + j];
#pragma unroll
                for (int hi = 0; hi < 12; hi++)
#pragma unroll
                    for (int dh = 0; dh < 3; dh++)
                        acc[hi] = fmaf(xr[hi + dh], wv[dw * 3 + dh], acc[hi]);
            }
        }
    }
    float wv_ = WV[c], bv_ = BV[c], bc_ = Bc[c];
#pragma unroll
    for (int hi = 0; hi < 12; hi++)
        g_V[(w * 96 + h0 + hi) * 64 + c] = fmaf(wv_, acc[hi] + bc_, bv_);
}

// ---------------- kernel 4: flash attention ----------------
// grid 144 (one 64-query tile), 768 threads = 3 independent 256-thread engines.
// engine e: key tiles kt = 3*it+e, it = 0..47; exact 3-way flash merge at end.
// X chunks: 32f x 64k (8 per kt), double-buffered, 2-deep LDG pipeline.
// smem floats: sQ 16384 | per engine: sX 2x2048 | sPT 64x68 | sVT 64x68
static const int ENG_SZ = 4096 + 4352 + 4352;                 // 12800 floats
static const int ATTN_SMEM_BYTES = (16384 + 3 * ENG_SZ) * 4;  // 219136 B
static const int NC = 48 * 8;   // chunks per engine

__device__ __forceinline__ void ldg_chunk(const float* __restrict__ X,
                                          int cc, int h, int ll, float4* rv) {
    int kt = 3 * (cc >> 3) + h;
    int fb = (cc & 7) << 5;
    int q0 = kt << 6;
#pragma unroll
    for (int t = 0; t < 2; t++) {
        int idx = ll + t * 256;
        int f = idx >> 4, k4 = (idx & 15) << 2;
        rv[t] = *(const float4*)(X + (fb + f) * 9216 + q0 + k4);
    }
}
__device__ __forceinline__ void sts_chunk(float* dst, int ll, const float4* rv) {
#pragma unroll
    for (int t = 0; t < 2; t++) {
        int idx = ll + t * 256;
        int f = idx >> 4, k4 = (idx & 15) << 2;
        *(float4*)(dst + f * 64 + k4) = rv[t];
    }
}

__global__ void __launch_bounds__(768, 1)
attn_kernel(const float* __restrict__ X, float* __restrict__ out) {
    extern __shared__ float sm[];
    const int tid = threadIdx.x;
    const int h = tid >> 8;          // engine id 0/1/2
    const int ll = tid & 255;
    const int ty = ll >> 4;          // queries ty*4..+3
    const int tx = ll & 15;          // keys tx*4..+3; channels tx*4..+3
    const int bid = h + 1;
    const int p0 = blockIdx.x * 64;

    float* sQ = sm;
    float* eb = sm + 16384 + h * ENG_SZ;
    float* sXb[2] = { eb, eb + 2048 };
    float* sPT = eb + 4096;    // [64][68]
    float* sVT = eb + 8448;    // [64][68]

    // --- prologue ---
    float4 rv[2];
    ldg_chunk(X, 0, h, ll, rv);

    for (int i = tid; i < 4096; i += 768) {
        int f = i >> 4, q = (i & 15) * 4;
        *(float4*)(sQ + f * 64 + q) = *(const float4*)(g_Qp + f * 9216 + p0 + q);
    }
    __syncthreads();

    sts_chunk(sXb[0], ll, rv);
    ldg_chunk(X, 1, h, ll, rv);
    HBAR(bid);

    ULL acc2[2][4];
#pragma unroll
    for (int r = 0; r < 2; r++)
#pragma unroll
        for (int j = 0; j < 4; j++) acc2[r][j] = 0ULL;
    float m[4], lsum[4];
#pragma unroll
    for (int i = 0; i < 4; i++) { m[i] = -1e30f; lsum[i] = 0.f; }

    for (int it = 0; it < 48; it++) {
        const int q0 = (3 * it + h) * 64;

        ULL S2[2][4];
#pragma unroll
        for (int r = 0; r < 2; r++)
#pragma unroll
            for (int j = 0; j < 4; j++) S2[r][j] = 0ULL;

        // ---- QK: 8 chunks of 32 features ----
        for (int c8 = 0; c8 < 8; c8++) {
            const int cc = it * 8 + c8;
            if (cc + 1 < NC) sts_chunk(sXb[(cc + 1) & 1], ll, rv);
            if (cc + 2 < NC) ldg_chunk(X, cc + 2, h, ll, rv);

            const float* sQb = sQ + (c8 * 32) * 64;
            const float* sXc = sXb[cc & 1];
#pragma unroll 16
            for (int fl = 0; fl < 32; fl++) {
                ulonglong2 a = *(const ulonglong2*)(sQb + fl * 64 + ty * 4);
                float4 b = *(const float4*)(sXc + fl * 64 + tx * 4);
                ULL b0 = pack2(b.x, b.x), b1 = pack2(b.y, b.y);
                ULL b2 = pack2(b.z, b.z), b3 = pack2(b.w, b.w);
                fma2(S2[0][0], a.x, b0); fma2(S2[1][0], a.y, b0);
                fma2(S2[0][1], a.x, b1); fma2(S2[1][1], a.y, b1);
                fma2(S2[0][2], a.x, b2); fma2(S2[1][2], a.y, b2);
                fma2(S2[0][3], a.x, b3); fma2(S2[1][3], a.y, b3);
            }
            if (c8 < 7) HBAR(bid);
        }

        // ---- stage V tile (overlaps softmax latency) ----
#pragma unroll
        for (int t = 0; t < 4; t++) {
            int idx = ll + t * 256;
            int k = idx >> 4, c4 = (idx & 15) << 2;
            *(float4*)(sVT + k * 68 + c4) = *(const float4*)(g_V + (q0 + k) * 64 + c4);
        }

        // ---- online softmax ----
        float s[4][4];
#pragma unroll
        for (int r = 0; r < 2; r++)
#pragma unroll
            for (int j = 0; j < 4; j++)
                unpack2(S2[r][j], s[2 * r][j], s[2 * r + 1][j]);

        float sc[4];
#pragma unroll
        for (int i = 0; i < 4; i++) {
            float rm = fmaxf(fmaxf(s[i][0], s[i][1]), fmaxf(s[i][2], s[i][3]));
#pragma unroll
            for (int o = 8; o > 0; o >>= 1)
                rm = fmaxf(rm, __shfl_xor_sync(0xffffffffu, rm, o));
            float mn = fmaxf(m[i], rm);
            float r0 = 0.f;
#pragma unroll
            for (int j = 0; j < 4; j++) {
                s[i][j] = __expf(s[i][j] - mn);
                r0 += s[i][j];
            }
#pragma unroll
            for (int o = 8; o > 0; o >>= 1)
                r0 += __shfl_xor_sync(0xffffffffu, r0, o);
            sc[i] = __expf(m[i] - mn);
            lsum[i] = fmaf(lsum[i], sc[i], r0);
            m[i] = mn;
        }
        ULL sc2[2] = { pack2(sc[0], sc[1]), pack2(sc[2], sc[3]) };
#pragma unroll
        for (int r = 0; r < 2; r++)
#pragma unroll
            for (int j = 0; j < 4; j++) mul2(acc2[r][j], sc2[r]);

        // ---- write P transposed: sPT[k][q] ----
#pragma unroll
        for (int j = 0; j < 4; j++) {
            float4 v = make_float4(s[0][j], s[1][j], s[2][j], s[3][j]);
            *(float4*)(sPT + (tx * 4 + j) * 68 + ty * 4) = v;
        }
        HBAR(bid);  // sPT + sVT ready

        // ---- PV ----
#pragma unroll 16
        for (int k = 0; k < 64; k++) {
            ulonglong2 pp = *(const ulonglong2*)(sPT + k * 68 + ty * 4);
            float4 v = *(const float4*)(sVT + k * 68 + tx * 4);
            ULL v0 = pack2(v.x, v.x), v1 = pack2(v.y, v.y);
            ULL v2 = pack2(v.z, v.z), v3 = pack2(v.w, v.w);
            fma2(acc2[0][0], pp.x, v0); fma2(acc2[1][0], pp.y, v0);
            fma2(acc2[0][1], pp.x, v1); fma2(acc2[1][1], pp.y, v1);
            fma2(acc2[0][2], pp.x, v2); fma2(acc2[1][2], pp.y, v2);
            fma2(acc2[0][3], pp.x, v3); fma2(acc2[1][3], pp.y, v3);
        }
        HBAR(bid);  // PV readers done before next kt overwrites sPT/sVT/sX
    }

    // ---- epilogue: 3-way exact flash merge ----
    __syncthreads();
    float* ex = sm;  // reuse sQ: engines 1,2 -> 2 * 256 * 24 floats
    if (h >= 1) {
        float* b = ex + ((h - 1) * 256 + ll) * 24;
#pragma unroll
        for (int i = 0; i < 4; i++) { b[i] = m[i]; b[4 + i] = lsum[i]; }
#pragma unroll
        for (int r = 0; r < 2; r++)
#pragma unroll
            for (int j = 0; j < 4; j++) {
                float lo, hi;
                unpack2(acc2[r][j], lo, hi);
                b[8 + (r * 4 + j) * 2] = lo;
                b[9 + (r * 4 + j) * 2] = hi;
            }
    }
    __syncthreads();
    if (h == 0) {
        const float* b1 = ex + ll * 24;
        const float* b2 = ex + (256 + ll) * 24;
        float w0[4], w1[4], w2[4], L[4];
#pragma unroll
        for (int i = 0; i < 4; i++) {
            float M = fmaxf(m[i], fmaxf(b1[i], b2[i]));
            w0[i] = __expf(m[i] - M);
            w1[i] = __expf(b1[i] - M);
            w2[i] = __expf(b2[i] - M);
            L[i] = lsum[i] * w0[i] + b1[4 + i] * w1[i] + b2[4 + i] * w2[i];
        }
#pragma unroll
        for (int r = 0; r < 2; r++)
#pragma unroll
            for (int j = 0; j < 4; j++) {
                float lo, hi;
                unpack2(acc2[r][j], lo, hi);
                int e = 8 + (r * 4 + j) * 2;
                int i0 = 2 * r, i1 = 2 * r + 1;
                float o0 = (lo * w0[i0] + b1[e] * w1[i0] + b2[e] * w2[i0]) / L[i0];
                float o1 = (hi * w0[i1] + b1[e + 1] * w1[i1] + b2[e + 1] * w2[i1]) / L[i1];
                int cc = tx * 4 + j;
                out[cc * 9216 + p0 + ty * 4 + i0] = o0;
                out[cc * 9216 + p0 + ty * 4 + i1] = o1;
            }
    }
}

// ---------------- launch ----------------
extern "C" void kernel_launch(void* const* d_in, const int* in_sizes, int n_in,
                              void* d_out, int out_size) {
    const float* X        = (const float*)d_in[0];
    const float* WQ_task  = (const float*)d_in[1];
    const float* BQ_task  = (const float*)d_in[2];
    const float* WK_task  = (const float*)d_in[3];
    // d_in[4]=BK_task, d_in[11]=BK: row-constant in logits -> cancel in softmax
    const float* WV_task  = (const float*)d_in[5];
    const float* BV_task  = (const float*)d_in[6];
    const float* WQ_tm1   = (const float*)d_in[7];
    const float* WQ_x     = (const float*)d_in[8];
    const float* BQ       = (const float*)d_in[9];
    const float* WK_x     = (const float*)d_in[10];
    const float* prevQ    = (const float*)d_in[12];
    const float* Vconv_w  = (const float*)d_in[13];
    const float* Vconv_b  = (const float*)d_in[14];
    float* out = (float*)d_out;

    coef_kernel<<<1, 256>>>(WQ_task, BQ_task, WK_task, WQ_tm1, WQ_x, BQ, WK_x);
    qprep_kernel<<<dim3(36, 256), 256>>>(X, prevQ);
    conv_kernel<<<dim3(96, 2), 256>>>(X, Vconv_w, Vconv_b, WV_task, BV_task);

    cudaFuncSetAttribute(attn_kernel,
                         cudaFuncAttributeMaxDynamicSharedMemorySize,
                         ATTN_SMEM_BYTES);
    attn_kernel<<<144, 768, ATTN_SMEM_BYTES>>>(X, out);
}

// round 9
// speedup vs baseline: 1.0562x; 1.0562x over previous
#include <cuda_runtime.h>

#define ULL unsigned long long

__device__ float g_Qp[256 * 9216];
__device__ float g_V[9216 * 64];     // V[p][c]
__device__ float g_cA[8 * 256];
__device__ float g_cB[256];
__device__ float g_cC[256];

__device__ __forceinline__ ULL pack2(float lo, float hi) {
    ULL r;
    asm("mov.b64 %0, {%1, %2};" : "=l"(r)
        : "r"(__float_as_uint(lo)), "r"(__float_as_uint(hi)));
    return r;
}
__device__ __forceinline__ void unpack2(ULL v, float& lo, float& hi) {
    unsigned a, b;
    asm("mov.b64 {%0, %1}, %2;" : "=r"(a), "=r"(b) : "l"(v));
    lo = __uint_as_float(a);
    hi = __uint_as_float(b);
}
__device__ __forceinline__ void fma2(ULL& d, ULL a, ULL b) {
    asm("fma.rn.f32x2 %0, %1, %2, %0;" : "+l"(d) : "l"(a), "l"(b));
}
__device__ __forceinline__ void mul2(ULL& d, ULL a) {
    asm("mul.rn.f32x2 %0, %0, %1;" : "+l"(d) : "l"(a));
}

#define HBAR(id) asm volatile("bar.sync %0, 256;" :: "r"(id) : "memory")

// ---------------- kernel 1: per-feature coefficients ----------------
__global__ void coef_kernel(const float* __restrict__ WQ_task,
                            const float* __restrict__ BQ_task,
                            const float* __restrict__ WK_task,
                            const float* __restrict__ WQ_tm1,
                            const float* __restrict__ WQ_x,
                            const float* __restrict__ BQ,
                            const float* __restrict__ WK_x) {
    int f = threadIdx.x;
    float kA = WK_task[f] * WK_x[f];
    float sW = 0.f, sB = 0.f;
#pragma unroll
    for (int h = 0; h < 8; h++) {
        float wq = WQ_task[h * 256 + f];
        sW += wq;
        sB += wq * BQ[h * 256 + f] + BQ_task[h * 256 + f];
        g_cA[h * 256 + f] = kA * wq * WQ_tm1[h * 256 + f];
    }
    g_cB[f] = kA * WQ_x[f] * sW;
    g_cC[f] = kA * sB;
}

// ---------------- kernel 2: build Q' ----------------
__global__ void qprep_kernel(const float* __restrict__ X,
                             const float* __restrict__ prevQ) {
    int f = blockIdx.y;
    int p = blockIdx.x * 256 + threadIdx.x;
    float q = fmaf(g_cB[f], X[f * 9216 + p], g_cC[f]);
#pragma unroll
    for (int h = 0; h < 8; h++)
        q = fmaf(g_cA[h * 256 + f], prevQ[(h * 256 + f) * 9216 + p], q);
    g_Qp[f * 9216 + p] = q;
}

// ---------------- kernel 3: 3x3 conv (F=256->C=64) + affine, writes V[p][c] ----------------
__global__ void __launch_bounds__(256) conv_kernel(const float* __restrict__ X,
                                                   const float* __restrict__ Wc,
                                                   const float* __restrict__ Bc,
                                                   const float* __restrict__ WV,
                                                   const float* __restrict__ BV) {
    __shared__ float sx[4 * 294];
    __shared__ float sw[4 * 288];
    const int tid = threadIdx.x;
    const int w = blockIdx.x;
    const int cbase = blockIdx.y * 32;
    const int cl = tid >> 3;
    const int c = cbase + cl;
    const int h0 = (tid & 7) * 12;

    float acc[12];
#pragma unroll
    for (int i = 0; i < 12; i++) acc[i] = 0.f;

    for (int fc = 0; fc < 256; fc += 4) {
        __syncthreads();
        for (int i = tid; i < 4 * 294; i += 256) {
            int ff = i / 294, r = i % 294;
            int dw = r / 98, hh = r % 98;
            int ww = w + dw - 1;
            float v = 0.f;
            if (ww >= 0 && ww < 96 && hh >= 1 && hh <= 96)
                v = X[(fc + ff) * 9216 + ww * 96 + hh - 1];
            sx[i] = v;
        }
        for (int i = tid; i < 4 * 288; i += 256) {
            int ff = i / 288, r = i % 288;
            int ccl = r / 9, s = r % 9;
            sw[i] = Wc[((cbase + ccl) * 256 + fc + ff) * 9 + s];
        }
        __syncthreads();
#pragma unroll
        for (int ff = 0; ff < 4; ff++) {
            float wv[9];
#pragma unroll
            for (int s = 0; s < 9; s++) wv[s] = sw[ff * 288 + cl * 9 + s];
#pragma unroll
            for (int dw = 0; dw < 3; dw++) {
                float xr[14];
#pragma unroll
                for (int j = 0; j < 14; j++) xr[j] = sx[ff * 294 + dw * 98 + h0 + j];
#pragma unroll
                for (int hi = 0; hi < 12; hi++)
#pragma unroll
                    for (int dh = 0; dh < 3; dh++)
                        acc[hi] = fmaf(xr[hi + dh], wv[dw * 3 + dh], acc[hi]);
            }
        }
    }
    float wv_ = WV[c], bv_ = BV[c], bc_ = Bc[c];
#pragma unroll
    for (int hi = 0; hi < 12; hi++)
        g_V[(w * 96 + h0 + hi) * 64 + c] = fmaf(wv_, acc[hi] + bc_, bv_);
}

// ---------------- kernel 4: flash attention ----------------
// grid 144 (one 64-query tile), 768 threads = 3 independent 256-thread engines.
// engine e: key tiles kt = 3*it+e, it = 0..47; exact 3-way flash merge at end.
// X chunks: 32f x 64k (8 per kt), double-buffered, 2-deep LDG pipeline.
// smem floats: sQ 16384 | per engine: sX 2x2048 | sPT 64x68 | sVT 64x68
static const int ENG_SZ = 4096 + 4352 + 4352;                 // 12800 floats
static const int ATTN_SMEM_BYTES = (16384 + 3 * ENG_SZ) * 4;  // 219136 B
static const int NC = 48 * 8;   // chunks per engine

__device__ __forceinline__ void ldg_chunk(const float* __restrict__ X,
                                          int cc, int h, int ll, float4* rv) {
    int kt = 3 * (cc >> 3) + h;
    int fb = (cc & 7) << 5;
    int q0 = kt << 6;
#pragma unroll
    for (int t = 0; t < 2; t++) {
        int idx = ll + t * 256;
        int f = idx >> 4, k4 = (idx & 15) << 2;
        rv[t] = *(const float4*)(X + (fb + f) * 9216 + q0 + k4);
    }
}
__device__ __forceinline__ void sts_chunk(float* dst, int ll, const float4* rv) {
#pragma unroll
    for (int t = 0; t < 2; t++) {
        int idx = ll + t * 256;
        int f = idx >> 4, k4 = (idx & 15) << 2;
        *(float4*)(dst + f * 64 + k4) = rv[t];
    }
}

__global__ void __launch_bounds__(768, 1)
attn_kernel(const float* __restrict__ X, float* __restrict__ out) {
    extern __shared__ float sm[];
    const int tid = threadIdx.x;
    const int h = tid >> 8;          // engine id 0/1/2
    const int ll = tid & 255;
    const int ty = ll >> 4;          // queries ty*4..+3
    const int tx = ll & 15;          // keys tx*4..+3; channels tx*4..+3
    const int bid = h + 1;
    const int p0 = blockIdx.x * 64;

    float* sQ = sm;
    float* eb = sm + 16384 + h * ENG_SZ;
    float* sXb[2] = { eb, eb + 2048 };
    float* sPT = eb + 4096;    // [64][68]
    float* sVT = eb + 8448;    // [64][68]

    // --- prologue ---
    float4 rv[2];
    ldg_chunk(X, 0, h, ll, rv);

    for (int i = tid; i < 4096; i += 768) {
        int f = i >> 4, q = (i & 15) * 4;
        *(float4*)(sQ + f * 64 + q) = *(const float4*)(g_Qp + f * 9216 + p0 + q);
    }
    __syncthreads();

    sts_chunk(sXb[0], ll, rv);
    ldg_chunk(X, 1, h, ll, rv);
    HBAR(bid);

    ULL acc2[2][4];
#pragma unroll
    for (int r = 0; r < 2; r++)
#pragma unroll
        for (int j = 0; j < 4; j++) acc2[r][j] = 0ULL;
    float m[4], lsum[4];
#pragma unroll
    for (int i = 0; i < 4; i++) { m[i] = -1e30f; lsum[i] = 0.f; }

    for (int it = 0; it < 48; it++) {
        const int q0 = (3 * it + h) * 64;

        ULL S2[2][4];
#pragma unroll
        for (int r = 0; r < 2; r++)
#pragma unroll
            for (int j = 0; j < 4; j++) S2[r][j] = 0ULL;

        // ---- QK: 8 chunks of 32 features ----
        for (int c8 = 0; c8 < 8; c8++) {
            const int cc = it * 8 + c8;
            if (cc + 1 < NC) sts_chunk(sXb[(cc + 1) & 1], ll, rv);
            if (cc + 2 < NC) ldg_chunk(X, cc + 2, h, ll, rv);

            const float* sQb = sQ + (c8 * 32) * 64;
            const float* sXc = sXb[cc & 1];
#pragma unroll 16
            for (int fl = 0; fl < 32; fl++) {
                ulonglong2 a = *(const ulonglong2*)(sQb + fl * 64 + ty * 4);
                float4 b = *(const float4*)(sXc + fl * 64 + tx * 4);
                ULL b0 = pack2(b.x, b.x), b1 = pack2(b.y, b.y);
                ULL b2 = pack2(b.z, b.z), b3 = pack2(b.w, b.w);
                fma2(S2[0][0], a.x, b0); fma2(S2[1][0], a.y, b0);
                fma2(S2[0][1], a.x, b1); fma2(S2[1][1], a.y, b1);
                fma2(S2[0][2], a.x, b2); fma2(S2[1][2], a.y, b2);
                fma2(S2[0][3], a.x, b3); fma2(S2[1][3], a.y, b3);
            }
            if (c8 < 7) HBAR(bid);
        }

        // ---- stage V tile (overlaps softmax latency) ----
#pragma unroll
        for (int t = 0; t < 4; t++) {
            int idx = ll + t * 256;
            int k = idx >> 4, c4 = (idx & 15) << 2;
            *(float4*)(sVT + k * 68 + c4) = *(const float4*)(g_V + (q0 + k) * 64 + c4);
        }

        // ---- online softmax ----
        float s[4][4];
#pragma unroll
        for (int r = 0; r < 2; r++)
#pragma unroll
            for (int j = 0; j < 4; j++)
                unpack2(S2[r][j], s[2 * r][j], s[2 * r + 1][j]);

        float sc[4];
#pragma unroll
        for (int i = 0; i < 4; i++) {
            float rm = fmaxf(fmaxf(s[i][0], s[i][1]), fmaxf(s[i][2], s[i][3]));
#pragma unroll
            for (int o = 8; o > 0; o >>= 1)
                rm = fmaxf(rm, __shfl_xor_sync(0xffffffffu, rm, o));
            float mn = fmaxf(m[i], rm);
            float r0 = 0.f;
#pragma unroll
            for (int j = 0; j < 4; j++) {
                s[i][j] = __expf(s[i][j] - mn);
                r0 += s[i][j];
            }
#pragma unroll
            for (int o = 8; o > 0; o >>= 1)
                r0 += __shfl_xor_sync(0xffffffffu, r0, o);
            sc[i] = __expf(m[i] - mn);
            lsum[i] = fmaf(lsum[i], sc[i], r0);
            m[i] = mn;
        }
        ULL sc2[2] = { pack2(sc[0], sc[1]), pack2(sc[2], sc[3]) };
#pragma unroll
        for (int r = 0; r < 2; r++)
#pragma unroll
            for (int j = 0; j < 4; j++) mul2(acc2[r][j], sc2[r]);

        // ---- write P transposed: sPT[k][q] ----
#pragma unroll
        for (int j = 0; j < 4; j++) {
            float4 v = make_float4(s[0][j], s[1][j], s[2][j], s[3][j]);
            *(float4*)(sPT + (tx * 4 + j) * 68 + ty * 4) = v;
        }
        HBAR(bid);  // sPT + sVT ready

        // ---- PV ----
#pragma unroll 16
        for (int k = 0; k < 64; k++) {
            ulonglong2 pp = *(const ulonglong2*)(sPT + k * 68 + ty * 4);
            float4 v = *(const float4*)(sVT + k * 68 + tx * 4);
            ULL v0 = pack2(v.x, v.x), v1 = pack2(v.y, v.y);
            ULL v2 = pack2(v.z, v.z), v3 = pack2(v.w, v.w);
            fma2(acc2[0][0], pp.x, v0); fma2(acc2[1][0], pp.y, v0);
            fma2(acc2[0][1], pp.x, v1); fma2(acc2[1][1], pp.y, v1);
            fma2(acc2[0][2], pp.x, v2); fma2(acc2[1][2], pp.y, v2);
            fma2(acc2[0][3], pp.x, v3); fma2(acc2[1][3], pp.y, v3);
        }
        HBAR(bid);  // PV readers done before next kt overwrites sPT/sVT/sX
    }

    // ---- epilogue: 3-way exact flash merge ----
    __syncthreads();
    float* ex = sm;  // reuse sQ: engines 1,2 -> 2 * 256 * 24 floats
    if (h >= 1) {
        float* b = ex + ((h - 1) * 256 + ll) * 24;
#pragma unroll
        for (int i = 0; i < 4; i++) { b[i] = m[i]; b[4 + i] = lsum[i]; }
#pragma unroll
        for (int r = 0; r < 2; r++)
#pragma unroll
            for (int j = 0; j < 4; j++) {
                float lo, hi;
                unpack2(acc2[r][j], lo, hi);
                b[8 + (r * 4 + j) * 2] = lo;
                b[9 + (r * 4 + j) * 2] = hi;
            }
    }
    __syncthreads();
    if (h == 0) {
        const float* b1 = ex + ll * 24;
        const float* b2 = ex + (256 + ll) * 24;
        float w0[4], w1[4], w2[4], L[4];
#pragma unroll
        for (int i = 0; i < 4; i++) {
            float M = fmaxf(m[i], fmaxf(b1[i], b2[i]));
            w0[i] = __expf(m[i] - M);
            w1[i] = __expf(b1[i] - M);
            w2[i] = __expf(b2[i] - M);
            L[i] = lsum[i] * w0[i] + b1[4 + i] * w1[i] + b2[4 + i] * w2[i];
        }
#pragma unroll
        for (int r = 0; r < 2; r++)
#pragma unroll
            for (int j = 0; j < 4; j++) {
                float lo, hi;
                unpack2(acc2[r][j], lo, hi);
                int e = 8 + (r * 4 + j) * 2;
                int i0 = 2 * r, i1 = 2 * r + 1;
                float o0 = (lo * w0[i0] + b1[e] * w1[i0] + b2[e] * w2[i0]) / L[i0];
                float o1 = (hi * w0[i1] + b1[e + 1] * w1[i1] + b2[e + 1] * w2[i1]) / L[i1];
                int cc = tx * 4 + j;
                out[cc * 9216 + p0 + ty * 4 + i0] = o0;
                out[cc * 9216 + p0 + ty * 4 + i1] = o1;
            }
    }
}

// ---------------- launch ----------------
extern "C" void kernel_launch(void* const* d_in, const int* in_sizes, int n_in,
                              void* d_out, int out_size) {
    const float* X        = (const float*)d_in[0];
    const float* WQ_task  = (const float*)d_in[1];
    const float* BQ_task  = (const float*)d_in[2];
    const float* WK_task  = (const float*)d_in[3];
    // d_in[4]=BK_task, d_in[11]=BK: row-constant in logits -> cancel in softmax
    const float* WV_task  = (const float*)d_in[5];
    const float* BV_task  = (const float*)d_in[6];
    const float* WQ_tm1   = (const float*)d_in[7];
    const float* WQ_x     = (const float*)d_in[8];
    const float* BQ       = (const float*)d_in[9];
    const float* WK_x     = (const float*)d_in[10];
    const float* prevQ    = (const float*)d_in[12];
    const float* Vconv_w  = (const float*)d_in[13];
    const float* Vconv_b  = (const float*)d_in[14];
    float* out = (float*)d_out;

    coef_kernel<<<1, 256>>>(WQ_task, BQ_task, WK_task, WQ_tm1, WQ_x, BQ, WK_x);
    qprep_kernel<<<dim3(36, 256), 256>>>(X, prevQ);
    conv_kernel<<<dim3(96, 2), 256>>>(X, Vconv_w, Vconv_b, WV_task, BV_task);

    cudaFuncSetAttribute(attn_kernel,
                         cudaFuncAttributeMaxDynamicSharedMemorySize,
                         ATTN_SMEM_BYTES);
    attn_kernel<<<144, 768, ATTN_SMEM_BYTES>>>(X, out);
}

// round 11
// speedup vs baseline: 1.2017x; 1.1377x over previous
#include <cuda_runtime.h>
#include <cstdint>

// ---------------- scratch ----------------
__device__ float g_Qp[256 * 9216];   // Q'[f][p]
__device__ float g_Qt[9216 * 256];   // Q'[p][f]
__device__ float g_Xt[9216 * 256];   // X [p][f]
__device__ float g_Vt[64 * 9216];    // V [c][p]
__device__ float g_cA[8 * 256], g_cB[256], g_cC[256];

// ---------------- helpers ----------------
__device__ __forceinline__ float tf32hi(float x) {
    uint32_t u;
    asm("cvt.rna.tf32.f32 %0, %1;" : "=r"(u) : "f"(x));
    return __uint_as_float(u);
}
__device__ __forceinline__ void split(float v, uint32_t& hi, uint32_t& lo) {
    float h = tf32hi(v);
    hi = __float_as_uint(h);
    lo = __float_as_uint(v - h);
}
// D(16x8,f32) += A(16x8,tf32,row) * B(8x8,tf32,col)
__device__ __forceinline__ void mma8(float* d, uint32_t a0, uint32_t a1,
                                     uint32_t a2, uint32_t a3,
                                     uint32_t b0, uint32_t b1) {
    asm volatile(
        "mma.sync.aligned.m16n8k8.row.col.f32.tf32.tf32.f32 "
        "{%0,%1,%2,%3}, {%4,%5,%6,%7}, {%8,%9}, {%0,%1,%2,%3};"
        : "+f"(d[0]), "+f"(d[1]), "+f"(d[2]), "+f"(d[3])
        : "r"(a0), "r"(a1), "r"(a2), "r"(a3), "r"(b0), "r"(b1));
}

// ---------------- kernel 1: per-feature coefficients ----------------
__global__ void coef_kernel(const float* __restrict__ WQ_task, const float* __restrict__ BQ_task,
                            const float* __restrict__ WK_task, const float* __restrict__ WQ_tm1,
                            const float* __restrict__ WQ_x, const float* __restrict__ BQ,
                            const float* __restrict__ WK_x) {
    int f = threadIdx.x;
    float kA = WK_task[f] * WK_x[f];
    float sW = 0.f, sB = 0.f;
#pragma unroll
    for (int h = 0; h < 8; h++) {
        float wq = WQ_task[h * 256 + f];
        sW += wq;
        sB += wq * BQ[h * 256 + f] + BQ_task[h * 256 + f];
        g_cA[h * 256 + f] = kA * wq * WQ_tm1[h * 256 + f];
    }
    g_cB[f] = kA * WQ_x[f] * sW;
    g_cC[f] = kA * sB;
}

// ---------------- kernel 2: Q' [f][p] ----------------
__global__ void qprep_kernel(const float* __restrict__ X, const float* __restrict__ prevQ) {
    int f = blockIdx.y;
    int p = blockIdx.x * 256 + threadIdx.x;
    float q = fmaf(g_cB[f], X[f * 9216 + p], g_cC[f]);
#pragma unroll
    for (int h = 0; h < 8; h++)
        q = fmaf(g_cA[h * 256 + f], prevQ[(h * 256 + f) * 9216 + p], q);
    g_Qp[f * 9216 + p] = q;
}

// ---------------- kernel 3: transpose [f][p] -> [p][f] ----------------
__global__ void trans_kernel(const float* __restrict__ src, float* __restrict__ dst) {
    __shared__ float t[32][33];
    int bx = blockIdx.x, by = blockIdx.y;
    int tx = threadIdx.x, ty = threadIdx.y;
#pragma unroll
    for (int j = 0; j < 4; j++)
        t[ty + j * 8][tx] = src[(by * 32 + ty + j * 8) * 9216 + bx * 32 + tx];
    __syncthreads();
#pragma unroll
    for (int j = 0; j < 4; j++)
        dst[(bx * 32 + ty + j * 8) * 256 + by * 32 + tx] = t[tx][ty + j * 8];
}

// ---------------- kernel 4: 3x3 conv (F=256->C=64) + affine -> g_Vt[c][p] ----------------
__global__ void __launch_bounds__(256) conv_kernel(const float* __restrict__ X,
                                                   const float* __restrict__ Wc,
                                                   const float* __restrict__ Bc,
                                                   const float* __restrict__ WV,
                                                   const float* __restrict__ BV) {
    __shared__ float sx[4 * 294];
    __shared__ float sw[4 * 288];
    const int tid = threadIdx.x;
    const int w = blockIdx.x;
    const int cbase = blockIdx.y * 32;
    const int cl = tid >> 3;
    const int c = cbase + cl;
    const int h0 = (tid & 7) * 12;
    float acc[12];
#pragma unroll
    for (int i = 0; i < 12; i++) acc[i] = 0.f;
    for (int fc = 0; fc < 256; fc += 4) {
        __syncthreads();
        for (int i = tid; i < 4 * 294; i += 256) {
            int ff = i / 294, r = i % 294;
            int dw = r / 98, hh = r % 98;
            int ww = w + dw - 1;
            float v = 0.f;
            if (ww >= 0 && ww < 96 && hh >= 1 && hh <= 96)
                v = X[(fc + ff) * 9216 + ww * 96 + hh - 1];
            sx[i] = v;
        }
        for (int i = tid; i < 4 * 288; i += 256) {
            int ff = i / 288, r = i % 288;
            sw[i] = Wc[((cbase + r / 9) * 256 + fc + ff) * 9 + r % 9];
        }
        __syncthreads();
#pragma unroll
        for (int ff = 0; ff < 4; ff++) {
            float wv[9];
#pragma unroll
            for (int s = 0; s < 9; s++) wv[s] = sw[ff * 288 + cl * 9 + s];
#pragma unroll
            for (int dw = 0; dw < 3; dw++) {
                float xr[14];
#pragma unroll
                for (int j = 0; j < 14; j++) xr[j] = sx[ff * 294 + dw * 98 + h0 + j];
#pragma unroll
                for (int hi = 0; hi < 12; hi++)
#pragma unroll
                    for (int dh = 0; dh < 3; dh++)
                        acc[hi] = fmaf(xr[hi + dh], wv[dw * 3 + dh], acc[hi]);
            }
        }
    }
    float wv_ = WV[c], bv_ = BV[c], bc_ = Bc[c];
#pragma unroll
    for (int hi = 0; hi < 12; hi++)
        g_Vt[c * 9216 + w * 96 + h0 + hi] = fmaf(wv_, acc[hi] + bc_, bv_);
}

// ---------------- kernel 5: flash attention via mma.sync tf32 ----------------
// grid 144: CTA = 64 queries x all 9216 keys (72 tiles of 128).
// 256 thr = 8 warps = 2 q-halves(32q) x 4 k-cols(32k). 3-pass tf32 split.
// smem floats: sQ 64x260 | sX 2x(128x36) | sP 64x132 | sV 64x132 | redM/redS 4x64
static const int SQ = 0, SX0 = 16640, SX1 = 21248, SP = 25856, SV = 34304;
static const int RM = 42752, RS = 43008;
static const int ATTN_SMEM = 43264 * 4;

__device__ __forceinline__ void ldgX(int cc, int tid, float4* rv) {
    int q0 = (cc >> 3) << 7, fb = (cc & 7) << 5;
#pragma unroll
    for (int j = 0; j < 4; j++) {
        int idx = tid + j * 256;
        int key = idx >> 3, f4 = idx & 7;
        rv[j] = *(const float4*)(g_Xt + (q0 + key) * 256 + fb + f4 * 4);
    }
}
__device__ __forceinline__ void stsX(float* dst, int tid, const float4* rv) {
#pragma unroll
    for (int j = 0; j < 4; j++) {
        int idx = tid + j * 256;
        int key = idx >> 3, f4 = idx & 7;
        *(float4*)(dst + key * 36 + f4 * 4) = rv[j];
    }
}

__global__ void __launch_bounds__(256, 1)
attn_kernel(float* __restrict__ out) {
    extern __shared__ float sm[];
    const int tid = threadIdx.x;
    const int w = tid >> 5, l = tid & 31;
    const int g = l >> 2, t = l & 3;
    const int qh = w >> 2, kc = w & 3;
    const int p0 = blockIdx.x * 64;

    float* sQ = sm + SQ;
    float* sXb[2] = { sm + SX0, sm + SX1 };
    float* sP = sm + SP;
    float* sV = sm + SV;
    float* redM = sm + RM;
    float* redS = sm + RS;

    // stage Q tile [64][260]
#pragma unroll
    for (int i = 0; i < 16; i++) {
        int idx = tid + i * 256;
        int q = idx >> 6, f4 = idx & 63;
        *(float4*)(sQ + q * 260 + f4 * 4) = *(const float4*)(g_Qt + (p0 + q) * 256 + f4 * 4);
    }

    float4 rv[4];
    ldgX(0, tid, rv);
    __syncthreads();

    float o[2][2][4];
#pragma unroll
    for (int a = 0; a < 2; a++)
#pragma unroll
        for (int b = 0; b < 2; b++)
#pragma unroll
            for (int j = 0; j < 4; j++) o[a][b][j] = 0.f;
    float m_[2][2], l_[2][2];
#pragma unroll
    for (int a = 0; a < 2; a++)
#pragma unroll
        for (int b = 0; b < 2; b++) { m_[a][b] = -1e30f; l_[a][b] = 0.f; }

    for (int kt = 0; kt < 72; kt++) {
        const int q0 = kt * 128;
        float s[2][4][4];
#pragma unroll
        for (int a = 0; a < 2; a++)
#pragma unroll
            for (int n = 0; n < 4; n++)
#pragma unroll
                for (int j = 0; j < 4; j++) s[a][n][j] = 0.f;

        // ---- QK: 8 chunks of 32 features ----
        for (int ch = 0; ch < 8; ch++) {
            const int cc = kt * 8 + ch;
            float* sX = sXb[cc & 1];
            stsX(sX, tid, rv);
            if (cc + 1 < 576) ldgX(cc + 1, tid, rv);
            __syncthreads();

#pragma unroll
            for (int ks = 0; ks < 4; ks++) {
                const int fo = ch * 32 + ks * 8;
                uint32_t ah[2][4], al[2][4], bh[4][2], bl[4][2];
#pragma unroll
                for (int qt = 0; qt < 2; qt++) {
                    const float* qr = sQ + (qh * 32 + qt * 16) * 260 + fo;
                    split(qr[g * 260 + t],           ah[qt][0], al[qt][0]);
                    split(qr[(g + 8) * 260 + t],     ah[qt][1], al[qt][1]);
                    split(qr[g * 260 + t + 4],       ah[qt][2], al[qt][2]);
                    split(qr[(g + 8) * 260 + t + 4], ah[qt][3], al[qt][3]);
                }
#pragma unroll
                for (int nt = 0; nt < 4; nt++) {
                    const float* xr = sX + (kc * 32 + nt * 8 + g) * 36 + ks * 8;
                    split(xr[t],     bh[nt][0], bl[nt][0]);
                    split(xr[t + 4], bh[nt][1], bl[nt][1]);
                }
#pragma unroll
                for (int qt = 0; qt < 2; qt++)
#pragma unroll
                    for (int nt = 0; nt < 4; nt++)
                        mma8(s[qt][nt], ah[qt][0], ah[qt][1], ah[qt][2], ah[qt][3],
                             bh[nt][0], bh[nt][1]);
#pragma unroll
                for (int qt = 0; qt < 2; qt++)
#pragma unroll
                    for (int nt = 0; nt < 4; nt++)
                        mma8(s[qt][nt], al[qt][0], al[qt][1], al[qt][2], al[qt][3],
                             bh[nt][0], bh[nt][1]);
#pragma unroll
                for (int qt = 0; qt < 2; qt++)
#pragma unroll
                    for (int nt = 0; nt < 4; nt++)
                        mma8(s[qt][nt], ah[qt][0], ah[qt][1], ah[qt][2], ah[qt][3],
                             bl[nt][0], bl[nt][1]);
            }
            __syncthreads();
        }

        // ---- softmax part 1: row maxes ----
        float rm[2][2];
#pragma unroll
        for (int qt = 0; qt < 2; qt++)
#pragma unroll
            for (int h2 = 0; h2 < 2; h2++) {
                float v = s[qt][0][2 * h2];
#pragma unroll
                for (int nt = 0; nt < 4; nt++) {
                    v = fmaxf(v, s[qt][nt][2 * h2]);
                    v = fmaxf(v, s[qt][nt][2 * h2 + 1]);
                }
                v = fmaxf(v, __shfl_xor_sync(0xffffffffu, v, 1));
                v = fmaxf(v, __shfl_xor_sync(0xffffffffu, v, 2));
                rm[qt][h2] = v;
            }
        if (t == 0) {
#pragma unroll
            for (int qt = 0; qt < 2; qt++)
#pragma unroll
                for (int h2 = 0; h2 < 2; h2++)
                    redM[kc * 64 + qh * 32 + qt * 16 + h2 * 8 + g] = rm[qt][h2];
        }
        __syncthreads();

        // ---- stage V tile [64c][128k] (LDG issues early, hides under exp) ----
#pragma unroll
        for (int j = 0; j < 8; j++) {
            int idx = tid + j * 256;
            int c = idx >> 5, k4 = idx & 31;
            float4 v = *(const float4*)(g_Vt + c * 9216 + q0 + k4 * 4);
            *(float4*)(sV + c * 132 + k4 * 4) = v;
        }

        // ---- softmax part 2: exp, sums, P to smem ----
        float mn[2][2], sc[2][2];
#pragma unroll
        for (int qt = 0; qt < 2; qt++)
#pragma unroll
            for (int h2 = 0; h2 < 2; h2++) {
                int row = qh * 32 + qt * 16 + h2 * 8 + g;
                float mx = fmaxf(fmaxf(redM[row], redM[64 + row]),
                                 fmaxf(redM[128 + row], redM[192 + row]));
                mn[qt][h2] = fmaxf(m_[qt][h2], mx);
                sc[qt][h2] = __expf(m_[qt][h2] - mn[qt][h2]);
                m_[qt][h2] = mn[qt][h2];
                float rs = 0.f;
#pragma unroll
                for (int nt = 0; nt < 4; nt++) {
                    float e0 = __expf(s[qt][nt][2 * h2] - mn[qt][h2]);
                    float e1 = __expf(s[qt][nt][2 * h2 + 1] - mn[qt][h2]);
                    s[qt][nt][2 * h2] = e0;
                    s[qt][nt][2 * h2 + 1] = e1;
                    rs += e0 + e1;
                }
                rs += __shfl_xor_sync(0xffffffffu, rs, 1);
                rs += __shfl_xor_sync(0xffffffffu, rs, 2);
                if (t == 0) redS[kc * 64 + row] = rs;
            }
        // write P: [q][k], 2 contiguous cols per store
#pragma unroll
        for (int qt = 0; qt < 2; qt++)
#pragma unroll
            for (int h2 = 0; h2 < 2; h2++) {
                int row = qh * 32 + qt * 16 + h2 * 8 + g;
#pragma unroll
                for (int nt = 0; nt < 4; nt++) {
                    float2 pv = make_float2(s[qt][nt][2 * h2], s[qt][nt][2 * h2 + 1]);
                    *(float2*)(sP + row * 132 + kc * 32 + nt * 8 + 2 * t) = pv;
                }
            }
        __syncthreads();

        // ---- flash update of l and O scale ----
#pragma unroll
        for (int qt = 0; qt < 2; qt++)
#pragma unroll
            for (int h2 = 0; h2 < 2; h2++) {
                int row = qh * 32 + qt * 16 + h2 * 8 + g;
                float rsum = redS[row] + redS[64 + row] + redS[128 + row] + redS[192 + row];
                l_[qt][h2] = l_[qt][h2] * sc[qt][h2] + rsum;
#pragma unroll
                for (int ct = 0; ct < 2; ct++) {
                    o[qt][ct][2 * h2] *= sc[qt][h2];
                    o[qt][ct][2 * h2 + 1] *= sc[qt][h2];
                }
            }

        // ---- PV: O += P(64x128) * V^T(128x64), warp covers 32q x 16c ----
#pragma unroll 4
        for (int ks = 0; ks < 16; ks++) {
            const int fo = ks * 8;
            uint32_t ph[2][4], pl[2][4], vh[2][2], vl[2][2];
#pragma unroll
            for (int qt = 0; qt < 2; qt++) {
                const float* pr = sP + (qh * 32 + qt * 16) * 132 + fo;
                split(pr[g * 132 + t],           ph[qt][0], pl[qt][0]);
                split(pr[(g + 8) * 132 + t],     ph[qt][1], pl[qt][1]);
                split(pr[g * 132 + t + 4],       ph[qt][2], pl[qt][2]);
                split(pr[(g + 8) * 132 + t + 4], ph[qt][3], pl[qt][3]);
            }
#pragma unroll
            for (int ct = 0; ct < 2; ct++) {
                const float* vr = sV + (kc * 16 + ct * 8 + g) * 132 + fo;
                split(vr[t],     vh[ct][0], vl[ct][0]);
                split(vr[t + 4], vh[ct][1], vl[ct][1]);
            }
#pragma unroll
            for (int qt = 0; qt < 2; qt++)
#pragma unroll
                for (int ct = 0; ct < 2; ct++)
                    mma8(o[qt][ct], ph[qt][0], ph[qt][1], ph[qt][2], ph[qt][3],
                         vh[ct][0], vh[ct][1]);
#pragma unroll
            for (int qt = 0; qt < 2; qt++)
#pragma unroll
                for (int ct = 0; ct < 2; ct++)
                    mma8(o[qt][ct], pl[qt][0], pl[qt][1], pl[qt][2], pl[qt][3],
                         vh[ct][0], vh[ct][1]);
#pragma unroll
            for (int qt = 0; qt < 2; qt++)
#pragma unroll
                for (int ct = 0; ct < 2; ct++)
                    mma8(o[qt][ct], ph[qt][0], ph[qt][1], ph[qt][2], ph[qt][3],
                         vl[ct][0], vl[ct][1]);
        }
    }

    // ---- epilogue: normalize, write out[c][p] ----
#pragma unroll
    for (int qt = 0; qt < 2; qt++)
#pragma unroll
        for (int h2 = 0; h2 < 2; h2++) {
            int pg = p0 + qh * 32 + qt * 16 + h2 * 8 + g;
            float inv = 1.f / l_[qt][h2];
#pragma unroll
            for (int ct = 0; ct < 2; ct++)
#pragma unroll
                for (int j = 0; j < 2; j++) {
                    int c = kc * 16 + ct * 8 + 2 * t + j;
                    out[c * 9216 + pg] = o[qt][ct][2 * h2 + j] * inv;
                }
        }
}

// ---------------- launch ----------------
extern "C" void kernel_launch(void* const* d_in, const int* in_sizes, int n_in,
                              void* d_out, int out_size) {
    const float* X       = (const float*)d_in[0];
    const float* WQ_task = (const float*)d_in[1];
    const float* BQ_task = (const float*)d_in[2];
    const float* WK_task = (const float*)d_in[3];
    // d_in[4]=BK_task, d_in[11]=BK: row-constant in logits -> cancel in softmax
    const float* WV_task = (const float*)d_in[5];
    const float* BV_task = (const float*)d_in[6];
    const float* WQ_tm1  = (const float*)d_in[7];
    const float* WQ_x    = (const float*)d_in[8];
    const float* BQ      = (const float*)d_in[9];
    const float* WK_x    = (const float*)d_in[10];
    const float* prevQ   = (const float*)d_in[12];
    const float* Vconv_w = (const float*)d_in[13];
    const float* Vconv_b = (const float*)d_in[14];
    float* out = (float*)d_out;

    coef_kernel<<<1, 256>>>(WQ_task, BQ_task, WK_task, WQ_tm1, WQ_x, BQ, WK_x);
    qprep_kernel<<<dim3(36, 256), 256>>>(X, prevQ);
    conv_kernel<<<dim3(96, 2), 256>>>(X, Vconv_w, Vconv_b, WV_task, BV_task);

    float* qt_ptr = nullptr, *xt_ptr = nullptr, *qp_ptr = nullptr;
    cudaGetSymbolAddress((void**)&qp_ptr, g_Qp);
    cudaGetSymbolAddress((void**)&qt_ptr, g_Qt);
    cudaGetSymbolAddress((void**)&xt_ptr, g_Xt);
    trans_kernel<<<dim3(288, 8), dim3(32, 8)>>>(qp_ptr, qt_ptr);
    trans_kernel<<<dim3(288, 8), dim3(32, 8)>>>(X, xt_ptr);

    cudaFuncSetAttribute(attn_kernel, cudaFuncAttributeMaxDynamicSharedMemorySize, ATTN_SMEM);
    attn_kernel<<<144, 256, ATTN_SMEM>>>(out);
}